// round 7
// baseline (speedup 1.0000x reference)
#include <cuda_runtime.h>
#include <math.h>

#define LRW 256
#define LRH 256
#define HRW 1024
#define HRH 1024
#define NC 3
#define RAD 4

#define LRN (NC * LRH * LRW)
#define WP 1032            // padded HR width: 4 + 1024 + 4
#define SC (255.0f / 1023.0f)

// Scratch (no cudaMalloc allowed) — device globals.
__device__ float g_A[LRN];
__device__ float g_B[LRN];
__device__ float g_HL[NC * 2 * LRH * WP];     // horiz-upsampled A,b (6.3 MB)

// ---------------------------------------------------------------------------
// Helpers
// ---------------------------------------------------------------------------
__device__ __forceinline__ void load12(float* v, const float* base) {
    float4 q0 = *reinterpret_cast<const float4*>(base);
    float4 q1 = *reinterpret_cast<const float4*>(base + 4);
    float4 q2 = *reinterpret_cast<const float4*>(base + 8);
    v[0]=q0.x; v[1]=q0.y; v[2]=q0.z;  v[3]=q0.w;
    v[4]=q1.x; v[5]=q1.y; v[6]=q1.z;  v[7]=q1.w;
    v[8]=q2.x; v[9]=q2.y; v[10]=q2.z; v[11]=q2.w;
}

// h[i] = sum v[i..i+4], i = 0..7  (sliding 5-window)
__device__ __forceinline__ void hsum5(float* h, const float* v) {
    h[0] = v[0] + v[1] + v[2] + v[3] + v[4];
#pragma unroll
    for (int i = 1; i < 8; ++i) h[i] = h[i - 1] - v[i - 1] + v[i + 4];
}

// ---------------------------------------------------------------------------
// Flat low-res kernel: NO smem, NO barriers. One thread = 4 output px.
// Vertical 9-sums of x, y, x*y, x*x accumulated in registers over 9 clamped
// rows; horizontal 9-sums by sliding window; A,b stored as float4.
// 49152 threads total (grid 384 x 128).
// ---------------------------------------------------------------------------
__global__ void __launch_bounds__(128) lr_flat(const float* __restrict__ lrx,
                                               const float* __restrict__ lry,
                                               const float* __restrict__ boxw) {
    const int t  = blockIdx.x * 128 + threadIdx.x;
    const int xg = t & 63;               // 64 groups of 4 px per row
    const int y  = (t >> 6) & 255;
    const int c  = t >> 14;
    const int x0 = xg << 2;

    const float* __restrict__ px = lrx + c * LRH * LRW;
    const float* __restrict__ py = lry + c * LRH * LRW;

    float sx[12], sy[12], sxy[12], sxx[12];
#pragma unroll
    for (int i = 0; i < 12; ++i) { sx[i]=0.f; sy[i]=0.f; sxy[i]=0.f; sxx[i]=0.f; }

    const bool interior = (x0 >= 4) && (x0 <= LRW - 12);

    if (interior) {
#pragma unroll
        for (int k = 0; k < 9; ++k) {
            int yy = y - 4 + k; yy = yy < 0 ? 0 : (yy > LRH - 1 ? LRH - 1 : yy);
            const float* rx = px + yy * LRW + (x0 - 4);
            const float* ry = py + yy * LRW + (x0 - 4);
            float vx[12], vy[12];
            load12(vx, rx);
            load12(vy, ry);
#pragma unroll
            for (int i = 0; i < 12; ++i) {
                sx[i] += vx[i]; sy[i] += vy[i];
                sxy[i] = fmaf(vx[i], vy[i], sxy[i]);
                sxx[i] = fmaf(vx[i], vx[i], sxx[i]);
            }
        }
    } else {
#pragma unroll
        for (int k = 0; k < 9; ++k) {
            int yy = y - 4 + k; yy = yy < 0 ? 0 : (yy > LRH - 1 ? LRH - 1 : yy);
            const float* rx = px + yy * LRW;
            const float* ry = py + yy * LRW;
#pragma unroll
            for (int i = 0; i < 12; ++i) {
                int xx = x0 - 4 + i; xx = xx < 0 ? 0 : (xx > LRW - 1 ? LRW - 1 : xx);
                float vx = rx[xx], vy = ry[xx];
                sx[i] += vx; sy[i] += vy;
                sxy[i] = fmaf(vx, vy, sxy[i]);
                sxx[i] = fmaf(vx, vx, sxx[i]);
            }
        }
    }

    // horizontal 9-sums for the 4 output px (sliding)
    float hx[4], hy[4], hxy[4], hxx[4];
    hx[0] = sx[0]+sx[1]+sx[2]+sx[3]+sx[4]+sx[5]+sx[6]+sx[7]+sx[8];
    hy[0] = sy[0]+sy[1]+sy[2]+sy[3]+sy[4]+sy[5]+sy[6]+sy[7]+sy[8];
    hxy[0]= sxy[0]+sxy[1]+sxy[2]+sxy[3]+sxy[4]+sxy[5]+sxy[6]+sxy[7]+sxy[8];
    hxx[0]= sxx[0]+sxx[1]+sxx[2]+sxx[3]+sxx[4]+sxx[5]+sxx[6]+sxx[7]+sxx[8];
#pragma unroll
    for (int i = 1; i < 4; ++i) {
        hx[i]  = hx[i-1]  - sx[i-1]  + sx[i+8];
        hy[i]  = hy[i-1]  - sy[i-1]  + sy[i+8];
        hxy[i] = hxy[i-1] - sxy[i-1] + sxy[i+8];
        hxx[i] = hxx[i-1] - sxx[i-1] + sxx[i+8];
    }

    const float w = boxw[c * 81];
    float A_[4], B_[4];
#pragma unroll
    for (int p = 0; p < 4; ++p) {
        float mx = hx[p] * w, my = hy[p] * w, mxy = hxy[p] * w, mxx = hxx[p] * w;
        float A = (mxy - mx * my) / (mxx - mx * mx + 2.0f);   // EPS = 2
        A_[p] = A; B_[p] = my - A * mx;
    }
    int o = c * LRH * LRW + y * LRW + x0;
    *reinterpret_cast<float4*>(&g_A[o]) = make_float4(A_[0], A_[1], A_[2], A_[3]);
    *reinterpret_cast<float4*>(&g_B[o]) = make_float4(B_[0], B_[1], B_[2], B_[3]);
}

// ---------------------------------------------------------------------------
// HL: horizontal bilinear of A,b at padded HR columns, all 256 LR rows.
// ---------------------------------------------------------------------------
#define NGX (WP / 4)   // 258

__global__ void __launch_bounds__(256) hl_kernel() {
    int t = blockIdx.x * 256 + threadIdx.x;
    if (t >= NC * LRH * NGX) return;
    int xg = t % NGX;
    int j  = (t / NGX) % LRH;
    int c  = t / (NGX * LRH);

    const float* __restrict__ pA = g_A + (c * LRH + j) * LRW;
    const float* __restrict__ pB = g_B + (c * LRH + j) * LRW;

    float a[4], b[4];
#pragma unroll
    for (int p = 0; p < 4; ++p) {
        int X = xg * 4 + p - 4;              // padded -> unpadded
        X = X < 0 ? 0 : (X > HRW - 1 ? HRW - 1 : X);
        float tt = (float)X * SC;
        int ix = (int)floorf(tt); if (ix > LRW - 2) ix = LRW - 2;
        float fx = tt - (float)ix, ofx = 1.0f - fx;
        a[p] = pA[ix] * ofx + pA[ix + 1] * fx;
        b[p] = pB[ix] * ofx + pB[ix + 1] * fx;
    }
    int oA = ((c * 2 + 0) * LRH + j) * WP + xg * 4;
    int oB = ((c * 2 + 1) * LRH + j) * WP + xg * 4;
    *reinterpret_cast<float4*>(&g_HL[oA]) = make_float4(a[0], a[1], a[2], a[3]);
    *reinterpret_cast<float4*>(&g_HL[oB]) = make_float4(b[0], b[1], b[2], b[3]);
}

// ---------------------------------------------------------------------------
// HR fused: block = 128-col x 16-row tile (grid 8x64x3), 256 threads.
// (unchanged from round 6)
// ---------------------------------------------------------------------------
#define XT 128
#define YS 16
#define SMP 140          // smem row stride (floats); 136 used
#define NQ 34            // 136 / 4 float4 groups
#define SR 20            // S rows: r in [Y0, Y0+19]
#define UR 16
#define UOFF (2 * SR * SMP)
#define NS_ITEMS (2 * SR * NQ)   // 1360
#define NU_ITEMS (2 * UR * NQ)   // 1088

__global__ void __launch_bounds__(256, 3) hr_fused(const float* __restrict__ hrx,
                                                   float* __restrict__ out) {
    __shared__ __align__(16) float sm[(2 * SR + 2 * UR) * SMP];  // 40.3 KB
    __shared__ int    s_j0[SR];
    __shared__ float4 s_w[SR];
    __shared__ int    s_ciy[UR];
    __shared__ float  s_cfy[UR];

    const int c  = blockIdx.z;
    const int X0 = blockIdx.x * XT;
    const int Y0 = blockIdx.y * YS;
    const int tid = threadIdx.x;

    // ---- Phase W: weight tables ----
    if (tid < SR) {
        int r = Y0 + tid;
        float w0 = 0.f, w1 = 0.f, w2 = 0.f, w3 = 0.f;
        int j0 = 0;
#pragma unroll
        for (int k = 0; k < 5; ++k) {
            int Y = r - 4 + k; Y = Y < 0 ? 0 : (Y > HRH - 1 ? HRH - 1 : Y);
            float tt = (float)Y * SC;
            int iy = (int)floorf(tt); if (iy > LRH - 2) iy = LRH - 2;
            float fy = tt - (float)iy;
            if (k == 0) j0 = iy;
            int d = iy - j0;
            w0 += (d == 0) ? (1.0f - fy) : 0.0f;
            w1 += (d == 0) ? fy : ((d == 1) ? (1.0f - fy) : 0.0f);
            w2 += (d == 1) ? fy : ((d == 2) ? (1.0f - fy) : 0.0f);
            w3 += (d == 2) ? fy : 0.0f;
        }
        s_j0[tid] = j0;
        s_w[tid] = make_float4(w0, w1, w2, w3);
    } else if (tid >= 32 && tid < 32 + UR) {
        int y = Y0 + (tid - 32);
        float tt = (float)y * SC;
        int iy = (int)floorf(tt); if (iy > LRH - 2) iy = LRH - 2;
        s_ciy[tid - 32] = iy;
        s_cfy[tid - 32] = tt - (float)iy;
    }
    __syncthreads();

    // ---- Phase F: fill S and U rows in smem ----
    const float* __restrict__ HLc = g_HL + (size_t)(c * 2) * LRH * WP + X0;
    for (int it = tid; it < NS_ITEMS + NU_ITEMS; it += 256) {
        if (it < NS_ITEMS) {
            int f  = it / (SR * NQ);
            int rm = it - f * (SR * NQ);
            int rr = rm / NQ;
            int q  = rm - rr * NQ;
            int j0 = s_j0[rr];
            float4 w = s_w[rr];
            const float* H = HLc + (size_t)f * LRH * WP + q * 4;
            int j1 = j0 + 1;
            int j2 = j0 + 2 > LRH - 1 ? LRH - 1 : j0 + 2;
            int j3 = j0 + 3 > LRH - 1 ? LRH - 1 : j0 + 3;
            float4 h0 = *reinterpret_cast<const float4*>(H + j0 * WP);
            float4 h1 = *reinterpret_cast<const float4*>(H + j1 * WP);
            float4 h2 = *reinterpret_cast<const float4*>(H + j2 * WP);
            float4 h3 = *reinterpret_cast<const float4*>(H + j3 * WP);
            float4 acc;
            acc.x = h0.x*w.x + h1.x*w.y + h2.x*w.z + h3.x*w.w;
            acc.y = h0.y*w.x + h1.y*w.y + h2.y*w.z + h3.y*w.w;
            acc.z = h0.z*w.x + h1.z*w.y + h2.z*w.z + h3.z*w.w;
            acc.w = h0.w*w.x + h1.w*w.y + h2.w*w.z + h3.w*w.w;
            *reinterpret_cast<float4*>(&sm[(f * SR + rr) * SMP + q * 4]) = acc;
        } else {
            int it2 = it - NS_ITEMS;
            int f  = it2 / (UR * NQ);
            int rm = it2 - f * (UR * NQ);
            int rr = rm / NQ;
            int q  = rm - rr * NQ;
            int iy = s_ciy[rr];
            float fy = s_cfy[rr], ofy = 1.0f - fy;
            const float* H = HLc + (size_t)f * LRH * WP + q * 4;
            float4 u0 = *reinterpret_cast<const float4*>(H + iy * WP);
            float4 u1 = *reinterpret_cast<const float4*>(H + (iy + 1) * WP);
            float4 u;
            u.x = u0.x*ofy + u1.x*fy; u.y = u0.y*ofy + u1.y*fy;
            u.z = u0.z*ofy + u1.z*fy; u.w = u0.w*ofy + u1.w*fy;
            *reinterpret_cast<float4*>(&sm[UOFF + (f * UR + rr) * SMP + q * 4]) = u;
        }
    }
    __syncthreads();

    // ---- Phase 3: 2 groups of 4 px per thread; warp == one row ----
    const float i45 = 1.0f / 45.0f, i25 = 1.0f / 25.0f;
#pragma unroll
    for (int g = 0; g < 2; ++g) {
        int G = g * 256 + tid;
        int row = G >> 5;                // 0..15
        int xl  = (G & 31) << 2;         // 0..124

        float vAt[12], vAb[12], vAc[12], vBt[12], vBb[12], vBc[12];
        load12(vAt, &sm[(0 * SR + row) * SMP + xl]);
        load12(vAb, &sm[(0 * SR + row + 4) * SMP + xl]);
        load12(vBt, &sm[(1 * SR + row) * SMP + xl]);
        load12(vBb, &sm[(1 * SR + row + 4) * SMP + xl]);
        load12(vAc, &sm[UOFF + (0 * UR + row) * SMP + xl]);
        load12(vBc, &sm[UOFF + (1 * UR + row) * SMP + xl]);

        float hAt[8], hAb[8], hAc[8], hBt[8], hBb[8], hBc[8];
        hsum5(hAt, vAt); hsum5(hAb, vAb); hsum5(hAc, vAc);
        hsum5(hBt, vBt); hsum5(hBb, vBb); hsum5(hBc, vBc);

        const int Y = Y0 + row, X = X0 + xl;
        const float4 im4 = *reinterpret_cast<const float4*>(
            &hrx[(c * HRH + Y) * HRW + X]);
        const float imv[4] = {im4.x, im4.y, im4.z, im4.w};

        float res[4];
#pragma unroll
        for (int p = 0; p < 4; ++p) {
            const float im = imv[p];
            float Ptl = fmaf(hAt[p],     im, hBt[p]);
            float Ptr = fmaf(hAt[p + 4], im, hBt[p + 4]);
            float Pbl = fmaf(hAb[p],     im, hBb[p]);
            float Pbr = fmaf(hAb[p + 4], im, hBb[p + 4]);
            float Pcl = fmaf(hAc[p],     im, hBc[p]);
            float Pcr = fmaf(hAc[p + 4], im, hBc[p + 4]);
            float Ptc = fmaf(vAt[p + 4], im, vBt[p + 4]);
            float Pbc = fmaf(vAb[p + 4], im, vBb[p + 4]);

            float d0 = fmaf(Ptl + Pbl - Pcl, i45, -im);  // L
            float d1 = fmaf(Ptr + Pbr - Pcr, i45, -im);  // R
            float d2 = fmaf(Ptl + Ptr - Ptc, i45, -im);  // U
            float d3 = fmaf(Pbl + Pbr - Pbc, i45, -im);  // D
            float d4 = fmaf(Ptl, i25, -im);              // NW
            float d5 = fmaf(Ptr, i25, -im);              // NE
            float d6 = fmaf(Pbl, i25, -im);              // SW
            float d7 = fmaf(Pbr, i25, -im);              // SE

            float best = d0, bestA = fabsf(d0), ad;
            ad = fabsf(d1); if (ad < bestA) { bestA = ad; best = d1; }
            ad = fabsf(d2); if (ad < bestA) { bestA = ad; best = d2; }
            ad = fabsf(d3); if (ad < bestA) { bestA = ad; best = d3; }
            ad = fabsf(d4); if (ad < bestA) { bestA = ad; best = d4; }
            ad = fabsf(d5); if (ad < bestA) { bestA = ad; best = d5; }
            ad = fabsf(d6); if (ad < bestA) { bestA = ad; best = d6; }
            ad = fabsf(d7); if (ad < bestA) { bestA = ad; best = d7; }

            float r = truncf(best + im);
            res[p] = fminf(fmaxf(r, 0.0f), 255.0f);
        }
        *reinterpret_cast<float4*>(&out[(c * HRH + Y) * HRW + X]) =
            make_float4(res[0], res[1], res[2], res[3]);
    }
}

// ---------------------------------------------------------------------------
extern "C" void kernel_launch(void* const* d_in, const int* in_sizes, int n_in,
                              void* d_out, int out_size) {
    const float* lrx  = (const float*)d_in[0];
    const float* lry  = (const float*)d_in[1];
    const float* hrx  = (const float*)d_in[2];
    const float* boxw = (const float*)d_in[3];
    float* out = (float*)d_out;

    lr_flat<<<LRN / 4 / 128, 128>>>(lrx, lry, boxw);

    int n_hl = NC * LRH * NGX;
    hl_kernel<<<(n_hl + 255) / 256, 256>>>();

    dim3 grid(HRW / XT, HRH / YS, NC);
    hr_fused<<<grid, 256>>>(hrx, out);
}

// round 8
// speedup vs baseline: 1.0580x; 1.0580x over previous
#include <cuda_runtime.h>
#include <math.h>

#define LRW 256
#define LRH 256
#define HRW 1024
#define HRH 1024
#define NC 3
#define RAD 4

#define LRN (NC * LRH * LRW)
#define WP 1032            // padded HR width: 4 + 1024 + 4
#define SC (255.0f / 1023.0f)

// Scratch (no cudaMalloc allowed) — device globals.
__device__ float g_A[LRN];
__device__ float g_B[LRN];
__device__ float g_HL[NC * 2 * LRH * WP];     // horiz-upsampled A,b (6.3 MB)

// ---------------------------------------------------------------------------
// Helpers
// ---------------------------------------------------------------------------
__device__ __forceinline__ void load12(float* v, const float* base) {
    float4 q0 = *reinterpret_cast<const float4*>(base);
    float4 q1 = *reinterpret_cast<const float4*>(base + 4);
    float4 q2 = *reinterpret_cast<const float4*>(base + 8);
    v[0]=q0.x; v[1]=q0.y; v[2]=q0.z;  v[3]=q0.w;
    v[4]=q1.x; v[5]=q1.y; v[6]=q1.z;  v[7]=q1.w;
    v[8]=q2.x; v[9]=q2.y; v[10]=q2.z; v[11]=q2.w;
}

// h[i] = sum v[i..i+4], i = 0..7  (sliding 5-window)
__device__ __forceinline__ void hsum5(float* h, const float* v) {
    h[0] = v[0] + v[1] + v[2] + v[3] + v[4];
#pragma unroll
    for (int i = 1; i < 8; ++i) h[i] = h[i - 1] - v[i - 1] + v[i + 4];
}

// ---------------------------------------------------------------------------
// Fused low-res kernel: tile 16x16 per block (grid 16x16x3 = 768 blocks),
// 128 threads. (proven round-6 version, reverted verbatim)
// ---------------------------------------------------------------------------
#define LTS 16
#define LEX 24
#define LSP 28

__global__ void __launch_bounds__(128) lr_fused(const float* __restrict__ lrx,
                                                const float* __restrict__ lry,
                                                const float* __restrict__ boxw) {
    __shared__ __align__(16) float Xs[LEX * LSP];
    __shared__ __align__(16) float Ys[LEX * LSP];
    __shared__ __align__(16) float Vx[LTS * LSP];
    __shared__ __align__(16) float Vy[LTS * LSP];
    __shared__ __align__(16) float Vxy[LTS * LSP];
    __shared__ __align__(16) float Vxx[LTS * LSP];

    const int c = blockIdx.z;
    const int x0t = blockIdx.x * LTS;
    const int y0t = blockIdx.y * LTS;
    const int tid = threadIdx.x;
    const float* __restrict__ px = lrx + c * LRH * LRW;
    const float* __restrict__ py = lry + c * LRH * LRW;

    for (int j = tid; j < LEX * LEX; j += 128) {
        int ly = j / LEX, lx = j % LEX;
        int Y = y0t - RAD + ly; Y = Y < 0 ? 0 : (Y > LRH - 1 ? LRH - 1 : Y);
        int X = x0t - RAD + lx; X = X < 0 ? 0 : (X > LRW - 1 ? LRW - 1 : X);
        Xs[ly * LSP + lx] = px[Y * LRW + X];
        Ys[ly * LSP + lx] = py[Y * LRW + X];
    }
    __syncthreads();

    for (int j = tid; j < LTS * LEX; j += 128) {
        int ry = j / LEX, lx = j % LEX;
        float sx = 0.f, sy = 0.f, sxy = 0.f, sxx = 0.f;
#pragma unroll
        for (int k = 0; k < 9; ++k) {
            float vx = Xs[(ry + k) * LSP + lx];
            float vy = Ys[(ry + k) * LSP + lx];
            sx += vx; sy += vy; sxy += vx * vy; sxx += vx * vx;
        }
        Vx[ry * LSP + lx] = sx;  Vy[ry * LSP + lx] = sy;
        Vxy[ry * LSP + lx] = sxy; Vxx[ry * LSP + lx] = sxx;
    }
    __syncthreads();

    if (tid < 64) {
        const int ty = tid >> 2;            // 0..15
        const int x0 = (tid & 3) << 2;      // 0,4,8,12
        float vx[12], vy[12], vxy[12], vxx[12];
        load12(vx,  &Vx[ty * LSP + x0]);
        load12(vy,  &Vy[ty * LSP + x0]);
        load12(vxy, &Vxy[ty * LSP + x0]);
        load12(vxx, &Vxx[ty * LSP + x0]);

        float hx[4], hy[4], hxy[4], hxx[4];
        hx[0] = vx[0]+vx[1]+vx[2]+vx[3]+vx[4]+vx[5]+vx[6]+vx[7]+vx[8];
        hy[0] = vy[0]+vy[1]+vy[2]+vy[3]+vy[4]+vy[5]+vy[6]+vy[7]+vy[8];
        hxy[0]= vxy[0]+vxy[1]+vxy[2]+vxy[3]+vxy[4]+vxy[5]+vxy[6]+vxy[7]+vxy[8];
        hxx[0]= vxx[0]+vxx[1]+vxx[2]+vxx[3]+vxx[4]+vxx[5]+vxx[6]+vxx[7]+vxx[8];
#pragma unroll
        for (int i = 1; i < 4; ++i) {
            hx[i]  = hx[i-1]  - vx[i-1]  + vx[i+8];
            hy[i]  = hy[i-1]  - vy[i-1]  + vy[i+8];
            hxy[i] = hxy[i-1] - vxy[i-1] + vxy[i+8];
            hxx[i] = hxx[i-1] - vxx[i-1] + vxx[i+8];
        }

        const float w = boxw[c * 81];
        float A_[4], B_[4];
#pragma unroll
        for (int p = 0; p < 4; ++p) {
            float mx = hx[p] * w, my = hy[p] * w, mxy = hxy[p] * w, mxx = hxx[p] * w;
            float A = (mxy - mx * my) / (mxx - mx * mx + 2.0f);   // EPS = 2
            A_[p] = A; B_[p] = my - A * mx;
        }
        int o = c * LRH * LRW + (y0t + ty) * LRW + (x0t + x0);
        *reinterpret_cast<float4*>(&g_A[o]) = make_float4(A_[0], A_[1], A_[2], A_[3]);
        *reinterpret_cast<float4*>(&g_B[o]) = make_float4(B_[0], B_[1], B_[2], B_[3]);
    }
}

// ---------------------------------------------------------------------------
// HL: horizontal bilinear of A,b at padded HR columns, all 256 LR rows.
// ---------------------------------------------------------------------------
#define NGX (WP / 4)   // 258

__global__ void __launch_bounds__(256) hl_kernel() {
    int t = blockIdx.x * 256 + threadIdx.x;
    if (t >= NC * LRH * NGX) return;
    int xg = t % NGX;
    int j  = (t / NGX) % LRH;
    int c  = t / (NGX * LRH);

    const float* __restrict__ pA = g_A + (c * LRH + j) * LRW;
    const float* __restrict__ pB = g_B + (c * LRH + j) * LRW;

    float a[4], b[4];
#pragma unroll
    for (int p = 0; p < 4; ++p) {
        int X = xg * 4 + p - 4;              // padded -> unpadded
        X = X < 0 ? 0 : (X > HRW - 1 ? HRW - 1 : X);
        float tt = (float)X * SC;
        int ix = (int)floorf(tt); if (ix > LRW - 2) ix = LRW - 2;
        float fx = tt - (float)ix, ofx = 1.0f - fx;
        a[p] = pA[ix] * ofx + pA[ix + 1] * fx;
        b[p] = pB[ix] * ofx + pB[ix + 1] * fx;
    }
    int oA = ((c * 2 + 0) * LRH + j) * WP + xg * 4;
    int oB = ((c * 2 + 1) * LRH + j) * WP + xg * 4;
    *reinterpret_cast<float4*>(&g_HL[oA]) = make_float4(a[0], a[1], a[2], a[3]);
    *reinterpret_cast<float4*>(&g_HL[oB]) = make_float4(b[0], b[1], b[2], b[3]);
}

// ---------------------------------------------------------------------------
// HR fused: block = 128-col x 16-row tile (grid 8x64x3), 256 threads.
// Change vs round 6: hrx tile PREFETCHED into registers at kernel entry,
// so its global-load latency is hidden behind phases W and F instead of
// landing on the phase-3 critical path.
// ---------------------------------------------------------------------------
#define XT 128
#define YS 16
#define SMP 140          // smem row stride (floats); 136 used
#define NQ 34            // 136 / 4 float4 groups
#define SR 20            // S rows: r in [Y0, Y0+19]
#define UR 16
#define UOFF (2 * SR * SMP)
#define NS_ITEMS (2 * SR * NQ)   // 1360
#define NU_ITEMS (2 * UR * NQ)   // 1088

__global__ void __launch_bounds__(256, 3) hr_fused(const float* __restrict__ hrx,
                                                   float* __restrict__ out) {
    __shared__ __align__(16) float sm[(2 * SR + 2 * UR) * SMP];  // 40.3 KB
    __shared__ int    s_j0[SR];
    __shared__ float4 s_w[SR];
    __shared__ int    s_ciy[UR];
    __shared__ float  s_cfy[UR];

    const int c  = blockIdx.z;
    const int X0 = blockIdx.x * XT;
    const int Y0 = blockIdx.y * YS;
    const int tid = threadIdx.x;

    // ---- Prefetch hrx tile for both phase-3 groups (independent of all
    // smem phases; latency hidden behind W + F). ----
    float4 im4g[2];
#pragma unroll
    for (int g = 0; g < 2; ++g) {
        int G = g * 256 + tid;
        int row = G >> 5;
        int xl  = (G & 31) << 2;
        im4g[g] = *reinterpret_cast<const float4*>(
            &hrx[(c * HRH + Y0 + row) * HRW + X0 + xl]);
    }

    // ---- Phase W: weight tables ----
    if (tid < SR) {
        int r = Y0 + tid;
        float w0 = 0.f, w1 = 0.f, w2 = 0.f, w3 = 0.f;
        int j0 = 0;
#pragma unroll
        for (int k = 0; k < 5; ++k) {
            int Y = r - 4 + k; Y = Y < 0 ? 0 : (Y > HRH - 1 ? HRH - 1 : Y);
            float tt = (float)Y * SC;
            int iy = (int)floorf(tt); if (iy > LRH - 2) iy = LRH - 2;
            float fy = tt - (float)iy;
            if (k == 0) j0 = iy;
            int d = iy - j0;
            w0 += (d == 0) ? (1.0f - fy) : 0.0f;
            w1 += (d == 0) ? fy : ((d == 1) ? (1.0f - fy) : 0.0f);
            w2 += (d == 1) ? fy : ((d == 2) ? (1.0f - fy) : 0.0f);
            w3 += (d == 2) ? fy : 0.0f;
        }
        s_j0[tid] = j0;
        s_w[tid] = make_float4(w0, w1, w2, w3);
    } else if (tid >= 32 && tid < 32 + UR) {
        int y = Y0 + (tid - 32);
        float tt = (float)y * SC;
        int iy = (int)floorf(tt); if (iy > LRH - 2) iy = LRH - 2;
        s_ciy[tid - 32] = iy;
        s_cfy[tid - 32] = tt - (float)iy;
    }
    __syncthreads();

    // ---- Phase F: fill S and U rows in smem ----
    const float* __restrict__ HLc = g_HL + (size_t)(c * 2) * LRH * WP + X0;
    for (int it = tid; it < NS_ITEMS + NU_ITEMS; it += 256) {
        if (it < NS_ITEMS) {
            int f  = it / (SR * NQ);
            int rm = it - f * (SR * NQ);
            int rr = rm / NQ;
            int q  = rm - rr * NQ;
            int j0 = s_j0[rr];
            float4 w = s_w[rr];
            const float* H = HLc + (size_t)f * LRH * WP + q * 4;
            int j1 = j0 + 1;
            int j2 = j0 + 2 > LRH - 1 ? LRH - 1 : j0 + 2;
            int j3 = j0 + 3 > LRH - 1 ? LRH - 1 : j0 + 3;
            float4 h0 = *reinterpret_cast<const float4*>(H + j0 * WP);
            float4 h1 = *reinterpret_cast<const float4*>(H + j1 * WP);
            float4 h2 = *reinterpret_cast<const float4*>(H + j2 * WP);
            float4 h3 = *reinterpret_cast<const float4*>(H + j3 * WP);
            float4 acc;
            acc.x = h0.x*w.x + h1.x*w.y + h2.x*w.z + h3.x*w.w;
            acc.y = h0.y*w.x + h1.y*w.y + h2.y*w.z + h3.y*w.w;
            acc.z = h0.z*w.x + h1.z*w.y + h2.z*w.z + h3.z*w.w;
            acc.w = h0.w*w.x + h1.w*w.y + h2.w*w.z + h3.w*w.w;
            *reinterpret_cast<float4*>(&sm[(f * SR + rr) * SMP + q * 4]) = acc;
        } else {
            int it2 = it - NS_ITEMS;
            int f  = it2 / (UR * NQ);
            int rm = it2 - f * (UR * NQ);
            int rr = rm / NQ;
            int q  = rm - rr * NQ;
            int iy = s_ciy[rr];
            float fy = s_cfy[rr], ofy = 1.0f - fy;
            const float* H = HLc + (size_t)f * LRH * WP + q * 4;
            float4 u0 = *reinterpret_cast<const float4*>(H + iy * WP);
            float4 u1 = *reinterpret_cast<const float4*>(H + (iy + 1) * WP);
            float4 u;
            u.x = u0.x*ofy + u1.x*fy; u.y = u0.y*ofy + u1.y*fy;
            u.z = u0.z*ofy + u1.z*fy; u.w = u0.w*ofy + u1.w*fy;
            *reinterpret_cast<float4*>(&sm[UOFF + (f * UR + rr) * SMP + q * 4]) = u;
        }
    }
    __syncthreads();

    // ---- Phase 3: 2 groups of 4 px per thread; warp == one row ----
    const float i45 = 1.0f / 45.0f, i25 = 1.0f / 25.0f;
#pragma unroll
    for (int g = 0; g < 2; ++g) {
        int G = g * 256 + tid;
        int row = G >> 5;                // 0..15
        int xl  = (G & 31) << 2;         // 0..124

        float vAt[12], vAb[12], vAc[12], vBt[12], vBb[12], vBc[12];
        load12(vAt, &sm[(0 * SR + row) * SMP + xl]);
        load12(vAb, &sm[(0 * SR + row + 4) * SMP + xl]);
        load12(vBt, &sm[(1 * SR + row) * SMP + xl]);
        load12(vBb, &sm[(1 * SR + row + 4) * SMP + xl]);
        load12(vAc, &sm[UOFF + (0 * UR + row) * SMP + xl]);
        load12(vBc, &sm[UOFF + (1 * UR + row) * SMP + xl]);

        float hAt[8], hAb[8], hAc[8], hBt[8], hBb[8], hBc[8];
        hsum5(hAt, vAt); hsum5(hAb, vAb); hsum5(hAc, vAc);
        hsum5(hBt, vBt); hsum5(hBb, vBb); hsum5(hBc, vBc);

        const float imv[4] = {im4g[g].x, im4g[g].y, im4g[g].z, im4g[g].w};

        float res[4];
#pragma unroll
        for (int p = 0; p < 4; ++p) {
            const float im = imv[p];
            float Ptl = fmaf(hAt[p],     im, hBt[p]);
            float Ptr = fmaf(hAt[p + 4], im, hBt[p + 4]);
            float Pbl = fmaf(hAb[p],     im, hBb[p]);
            float Pbr = fmaf(hAb[p + 4], im, hBb[p + 4]);
            float Pcl = fmaf(hAc[p],     im, hBc[p]);
            float Pcr = fmaf(hAc[p + 4], im, hBc[p + 4]);
            float Ptc = fmaf(vAt[p + 4], im, vBt[p + 4]);
            float Pbc = fmaf(vAb[p + 4], im, vBb[p + 4]);

            float d0 = fmaf(Ptl + Pbl - Pcl, i45, -im);  // L
            float d1 = fmaf(Ptr + Pbr - Pcr, i45, -im);  // R
            float d2 = fmaf(Ptl + Ptr - Ptc, i45, -im);  // U
            float d3 = fmaf(Pbl + Pbr - Pbc, i45, -im);  // D
            float d4 = fmaf(Ptl, i25, -im);              // NW
            float d5 = fmaf(Ptr, i25, -im);              // NE
            float d6 = fmaf(Pbl, i25, -im);              // SW
            float d7 = fmaf(Pbr, i25, -im);              // SE

            float best = d0, bestA = fabsf(d0), ad;
            ad = fabsf(d1); if (ad < bestA) { bestA = ad; best = d1; }
            ad = fabsf(d2); if (ad < bestA) { bestA = ad; best = d2; }
            ad = fabsf(d3); if (ad < bestA) { bestA = ad; best = d3; }
            ad = fabsf(d4); if (ad < bestA) { bestA = ad; best = d4; }
            ad = fabsf(d5); if (ad < bestA) { bestA = ad; best = d5; }
            ad = fabsf(d6); if (ad < bestA) { bestA = ad; best = d6; }
            ad = fabsf(d7); if (ad < bestA) { bestA = ad; best = d7; }

            float r = truncf(best + im);
            res[p] = fminf(fmaxf(r, 0.0f), 255.0f);
        }
        int row2 = row, xl2 = xl;
        *reinterpret_cast<float4*>(&out[(c * HRH + Y0 + row2) * HRW + X0 + xl2]) =
            make_float4(res[0], res[1], res[2], res[3]);
    }
}

// ---------------------------------------------------------------------------
extern "C" void kernel_launch(void* const* d_in, const int* in_sizes, int n_in,
                              void* d_out, int out_size) {
    const float* lrx  = (const float*)d_in[0];
    const float* lry  = (const float*)d_in[1];
    const float* hrx  = (const float*)d_in[2];
    const float* boxw = (const float*)d_in[3];
    float* out = (float*)d_out;

    dim3 lgrid(LRW / LTS, LRH / LTS, NC);
    lr_fused<<<lgrid, 128>>>(lrx, lry, boxw);

    int n_hl = NC * LRH * NGX;
    hl_kernel<<<(n_hl + 255) / 256, 256>>>();

    dim3 grid(HRW / XT, HRH / YS, NC);
    hr_fused<<<grid, 256>>>(hrx, out);
}